// round 7
// baseline (speedup 1.0000x reference)
#include <cuda_runtime.h>
#include <cuda_bf16.h>

#define NN   4
#define AA   16
#define HH   384
#define WW   384
#define BSZ  8
#define STR  4
#define NB   95
#define NBLK (NB*NB)
#define SEG  (NB*8)          // 760 floats: one (n,a,bi,li) row of block outputs
#define NSWEEP 7
#define THRESH_F 2.0f

// Block outputs staged here: layout [n][a][bi][li][bj][lj]
// size = 4*16*95*8*95*8 = 36,966,400 floats = ~148 MB (static device array: allowed)
__device__ float g_scratch[(size_t)NN * AA * NB * 8 * NB * 8];

// ---------------------------------------------------------------------------
// Pass 1: one CTA (128 threads) per (n, block). Gather m [64x16], G = m^T m,
// Jacobi eigensolve (warp 0), W = V diag(r) V^T, out = m W -> scratch.
// ---------------------------------------------------------------------------
__global__ __launch_bounds__(128) void llr_pass1(const float* __restrict__ x) {
    __shared__ float sm[64 * 17];   // m[p][a] at p*17+a (pad 17: conflict-free column reads)
    __shared__ float sG[16 * 17];
    __shared__ float sV[16 * 17];
    __shared__ float sW[16 * 17];
    __shared__ float s_cs[16];      // c[k] at [k], s[k] at [8+k]
    __shared__ float s_r[16];       // spectral ratios max(S-t,0)/S

    const int cta = blockIdx.x;
    const int n   = cta / NBLK;
    const int blk = cta - n * NBLK;
    const int bi  = blk / NB;
    const int bj  = blk - bi * NB;
    const int h0  = bi * STR;
    const int w0  = bj * STR;
    const int t   = threadIdx.x;

    // ---- gather m: 1024 elements; lj runs are 32B-contiguous in gmem
    #pragma unroll
    for (int i = 0; i < 8; i++) {
        int e = t + i * 128;
        int a = e >> 6;           // 0..15
        int p = e & 63;           // 0..63
        int li = p >> 3, lj = p & 7;
        sm[p * 17 + a] = x[((size_t)(n * AA + a) * HH + (h0 + li)) * WW + (w0 + lj)];
    }
    __syncthreads();

    // ---- G = m^T m (256 entries, 2 per thread), init V = I
    #pragma unroll
    for (int i = 0; i < 2; i++) {
        int e = t + i * 128;
        int j = e >> 4, k = e & 15;
        float acc = 0.f;
        #pragma unroll
        for (int p = 0; p < 64; p++) acc += sm[p * 17 + j] * sm[p * 17 + k];
        sG[j * 17 + k] = acc;
        sV[j * 17 + k] = (j == k) ? 1.f : 0.f;
    }
    __syncthreads();

    // ---- parallel cyclic Jacobi on warp 0: 8 disjoint rotations per round,
    //      tournament pairing, 15 rounds/sweep. Disjoint pairs -> only
    //      __syncwarp between phases, no CTA barrier in the hot loop.
    if (t < 32) {
        const int lane = t;
        const int k    = lane >> 2;      // pair id 0..7
        const int sub  = lane & 3;       // row/col segment 0..3
        const int r0   = sub * 4;

        for (int it = 0; it < NSWEEP * 15; it++) {
            int r = it % 15;
            int p, q;
            if (k == 0) { p = 15; q = r; }
            else        { p = (r + k) % 15; q = (r + 15 - k) % 15; }

            if (sub == 0) {
                float apq = sG[p * 17 + q];
                float c = 1.f, s = 0.f;
                if (fabsf(apq) > 1e-37f) {
                    float app = sG[p * 17 + p], aqq = sG[q * 17 + q];
                    float tau = (aqq - app) / (2.f * apq);
                    float tt  = 1.f / (fabsf(tau) + sqrtf(1.f + tau * tau));
                    if (tau < 0.f) tt = -tt;
                    c = rsqrtf(1.f + tt * tt);
                    s = tt * c;
                }
                s_cs[k]     = c;
                s_cs[8 + k] = s;
            }
            __syncwarp();
            const float c = s_cs[k], s = s_cs[8 + k];
            float np[4], nq[4];

            // Phase A: G <- G*J (columns p,q; this lane's 4 rows)
            #pragma unroll
            for (int i2 = 0; i2 < 4; i2++) {
                float a1 = sG[(r0 + i2) * 17 + p], a2 = sG[(r0 + i2) * 17 + q];
                np[i2] = c * a1 - s * a2;
                nq[i2] = s * a1 + c * a2;
            }
            #pragma unroll
            for (int i2 = 0; i2 < 4; i2++) {
                sG[(r0 + i2) * 17 + p] = np[i2];
                sG[(r0 + i2) * 17 + q] = nq[i2];
            }
            __syncwarp();

            // Phase B: G <- J^T*G (rows p,q; this lane's 4 columns)
            #pragma unroll
            for (int i2 = 0; i2 < 4; i2++) {
                float a1 = sG[p * 17 + r0 + i2], a2 = sG[q * 17 + r0 + i2];
                np[i2] = c * a1 - s * a2;
                nq[i2] = s * a1 + c * a2;
            }
            #pragma unroll
            for (int i2 = 0; i2 < 4; i2++) {
                sG[p * 17 + r0 + i2] = np[i2];
                sG[q * 17 + r0 + i2] = nq[i2];
            }
            __syncwarp();

            // Phase C: V <- V*J (eigenvector accumulation, columns p,q)
            #pragma unroll
            for (int i2 = 0; i2 < 4; i2++) {
                float a1 = sV[(r0 + i2) * 17 + p], a2 = sV[(r0 + i2) * 17 + q];
                np[i2] = c * a1 - s * a2;
                nq[i2] = s * a1 + c * a2;
            }
            #pragma unroll
            for (int i2 = 0; i2 < 4; i2++) {
                sV[(r0 + i2) * 17 + p] = np[i2];
                sV[(r0 + i2) * 17 + q] = nq[i2];
            }
            __syncwarp();
        }

        // spectral soft-threshold ratios: r_i = max(sqrt(l)-T, 0)/sqrt(l)
        if (lane < 16) {
            float lam = sG[lane * 17 + lane];
            float sv  = sqrtf(fmaxf(lam, 0.f));
            s_r[lane] = (sv > THRESH_F) ? (1.f - THRESH_F / sv) : 0.f;
        }
    }
    __syncthreads();

    // ---- W = V diag(r) V^T (256 entries, 2 per thread); s_r hoisted per-entry
    #pragma unroll
    for (int i = 0; i < 2; i++) {
        int e = t + i * 128;
        int j = e >> 4, kk = e & 15;
        float acc = 0.f;
        #pragma unroll
        for (int i2 = 0; i2 < 16; i2++)
            acc += sV[j * 17 + i2] * (s_r[i2] * sV[kk * 17 + i2]);
        sW[j * 17 + kk] = acc;
    }
    __syncthreads();

    // ---- out = m @ W -> scratch [n][a][bi][li][bj][lj] (32B-contiguous lj runs)
    #pragma unroll
    for (int i = 0; i < 8; i++) {
        int e = t + i * 128;
        int a = e >> 6;
        int p = e & 63;
        int li = p >> 3, lj = p & 7;
        float acc = 0.f;
        #pragma unroll
        for (int j = 0; j < 16; j++)
            acc += sm[p * 17 + j] * sW[j * 17 + a];
        g_scratch[(((size_t)(n * AA + a) * NB + bi) * 8 + li) * SEG + bj * 8 + lj] = acc;
    }
}

// ---------------------------------------------------------------------------
// Pass 2: one CTA per output row (n,a,h). Each scratch element feeds exactly
// one pixel, so this is a pure gather-sum: stage the <=2 contributing
// 760-float segments in smem, sum <=4 contributions per pixel, normalize.
// Deterministic (fixed summation order), atomic-free, fully coalesced.
// ---------------------------------------------------------------------------
__global__ __launch_bounds__(128) void llr_pass2(const float* __restrict__ bw,
                                                 float* __restrict__ out) {
    __shared__ float seg[2][SEG];

    const int cta = blockIdx.x;
    const int h   = cta % HH;
    const int na  = cta / HH;          // n*AA + a
    const int t   = threadIdx.x;

    const int bi_lo = max(0, (h - 4) >> 2);        // == ceil((h-7)/4)
    const int bi_hi = min(NB - 1, h >> 2);
    const int nbi   = bi_hi - bi_lo + 1;           // 1 or 2

    for (int b = 0; b < nbi; b++) {
        int bi = bi_lo + b;
        int li = h - bi * STR;
        const float* src = g_scratch + (((size_t)na * NB + bi) * 8 + li) * SEG;
        for (int i = t; i < SEG; i += 128) seg[b][i] = src[i];
    }
    __syncthreads();

    #pragma unroll
    for (int i = 0; i < 3; i++) {
        int w = t + i * 128;
        int bj_lo = max(0, (w - 4) >> 2);
        int bj_hi = min(NB - 1, w >> 2);
        float acc = 0.f;
        for (int b = 0; b < nbi; b++)
            for (int bj = bj_lo; bj <= bj_hi; bj++)
                acc += seg[b][bj * 8 + (w - bj * STR)];
        out[((size_t)na * HH + h) * WW + w] = acc / bw[h * WW + w];
    }
}

// ---------------------------------------------------------------------------
extern "C" void kernel_launch(void* const* d_in, const int* in_sizes, int n_in,
                              void* d_out, int out_size) {
    (void)n_in; (void)out_size;
    const float* x;
    const float* bw;
    if (in_sizes[0] == NN * AA * HH * WW) { x = (const float*)d_in[0]; bw = (const float*)d_in[1]; }
    else                                  { x = (const float*)d_in[1]; bw = (const float*)d_in[0]; }
    float* out = (float*)d_out;

    llr_pass1<<<NN * NBLK, 128>>>(x);
    llr_pass2<<<NN * AA * HH, 128>>>(bw, out);
}

// round 8
// speedup vs baseline: 1.5073x; 1.5073x over previous
#include <cuda_runtime.h>
#include <cuda_bf16.h>

#define NN   4
#define AA   16
#define HH   384
#define WW   384
#define BSZ  8
#define STR  4
#define NB   95
#define NBLK (NB*NB)
#define SEG  (NB*8)          // 760 floats: one (n,a,bi,li) row of block outputs
#define NSWEEP 6
#define THRESH_F 2.0f

// Block outputs staged here: layout [n][a][bi][li][bj][lj]
// size = 4*16*95*8*95*8 = 36,966,400 floats = ~148 MB (static device array: allowed)
__device__ float g_scratch[(size_t)NN * AA * NB * 8 * NB * 8];

// Per-warp smem slice layout (floats):
//   [0,1088)    m[64][17]   (pad 17 -> conflict-free column reads)
//   [1088,1360) G[16][17]   (reused for W after eigensolve)
//   [1360,1632) V[16][17]
//   [1632,1648) r[16]       spectral ratios
#define WSM 1648

// ---------------------------------------------------------------------------
// Pass 1: one WARP per (n, block). 4 matrices per CTA, fully independent
// warps: gather m [64x16], G = m^T m, parallel cyclic Jacobi (8 disjoint
// rotations/round), W = V diag(r) V^T, out = m @ W -> scratch.
// No __syncthreads anywhere; __syncwarp only.
// ---------------------------------------------------------------------------
__global__ __launch_bounds__(128) void llr_pass1(const float* __restrict__ x) {
    __shared__ float sh[4 * WSM];

    const int wid  = threadIdx.x >> 5;
    const int lane = threadIdx.x & 31;
    float* sm = sh + wid * WSM;
    float* sG = sm + 1088;        // becomes W later
    float* sV = sm + 1360;
    float* sR = sm + 1632;

    const int id  = blockIdx.x * 4 + wid;        // matrix id 0..36099
    const int n   = id / NBLK;
    const int blk = id - n * NBLK;
    const int bi  = blk / NB;
    const int bj  = blk - bi * NB;
    const int h0  = bi * STR;
    const int w0  = bj * STR;

    // ---- gather m: 1024 elements, 32 per lane; lj runs are 32B-contiguous
    #pragma unroll
    for (int i = 0; i < 32; i++) {
        int e = lane + i * 32;
        int a = e >> 6;           // 0..15
        int p = e & 63;           // 0..63
        int li = p >> 3, lj = p & 7;
        sm[p * 17 + a] = x[((size_t)(n * AA + a) * HH + (h0 + li)) * WW + (w0 + lj)];
    }
    __syncwarp();

    // ---- G = m^T m (256 entries, 8 per lane), init V = I
    #pragma unroll
    for (int i = 0; i < 8; i++) {
        int e = lane + i * 32;
        int j = e >> 4, kk = e & 15;
        float acc = 0.f;
        #pragma unroll
        for (int p = 0; p < 64; p++) acc += sm[p * 17 + j] * sm[p * 17 + kk];
        sG[j * 17 + kk] = acc;
        sV[j * 17 + kk] = (j == kk) ? 1.f : 0.f;
    }
    __syncwarp();

    // ---- parallel cyclic Jacobi: 8 disjoint rotations per round (tournament
    //      pairing), 15 rounds/sweep. All 4 lanes of a pair compute (c,s)
    //      redundantly from identical smem reads (bitwise identical).
    {
        const int k   = lane >> 2;      // pair id 0..7
        const int sub = lane & 3;       // row/col segment 0..3
        const int r0  = sub * 4;

        for (int it = 0; it < NSWEEP * 15; it++) {
            int r = it % 15;
            int p, q;
            if (k == 0) { p = 15; q = r; }
            else        { p = (r + k) % 15; q = (r + 15 - k) % 15; }

            float apq = sG[p * 17 + q];
            float c = 1.f, s = 0.f;
            if (fabsf(apq) > 1e-37f) {
                float app = sG[p * 17 + p], aqq = sG[q * 17 + q];
                float tau = (aqq - app) / (2.f * apq);
                float tt  = 1.f / (fabsf(tau) + sqrtf(1.f + tau * tau));
                if (tau < 0.f) tt = -tt;
                c = rsqrtf(1.f + tt * tt);
                s = tt * c;
            }
            __syncwarp();   // params fully read before any column write

            float np[4], nq[4];

            // Phase A: G <- G*J (columns p,q; this lane's 4 rows)
            #pragma unroll
            for (int i2 = 0; i2 < 4; i2++) {
                float a1 = sG[(r0 + i2) * 17 + p], a2 = sG[(r0 + i2) * 17 + q];
                np[i2] = c * a1 - s * a2;
                nq[i2] = s * a1 + c * a2;
            }
            #pragma unroll
            for (int i2 = 0; i2 < 4; i2++) {
                sG[(r0 + i2) * 17 + p] = np[i2];
                sG[(r0 + i2) * 17 + q] = nq[i2];
            }
            __syncwarp();

            // Phase B: G <- J^T*G (rows p,q; this lane's 4 columns)
            #pragma unroll
            for (int i2 = 0; i2 < 4; i2++) {
                float a1 = sG[p * 17 + r0 + i2], a2 = sG[q * 17 + r0 + i2];
                np[i2] = c * a1 - s * a2;
                nq[i2] = s * a1 + c * a2;
            }
            #pragma unroll
            for (int i2 = 0; i2 < 4; i2++) {
                sG[p * 17 + r0 + i2] = np[i2];
                sG[q * 17 + r0 + i2] = nq[i2];
            }
            __syncwarp();

            // Phase C: V <- V*J (eigenvector accumulation; independent of G,
            // next iteration's param read is fenced by the post-A syncwarp)
            #pragma unroll
            for (int i2 = 0; i2 < 4; i2++) {
                float a1 = sV[(r0 + i2) * 17 + p], a2 = sV[(r0 + i2) * 17 + q];
                np[i2] = c * a1 - s * a2;
                nq[i2] = s * a1 + c * a2;
            }
            #pragma unroll
            for (int i2 = 0; i2 < 4; i2++) {
                sV[(r0 + i2) * 17 + p] = np[i2];
                sV[(r0 + i2) * 17 + q] = nq[i2];
            }
            __syncwarp();
        }
    }

    // ---- spectral soft-threshold ratios: r_i = max(sqrt(l)-T, 0)/sqrt(l)
    if (lane < 16) {
        float lam = sG[lane * 17 + lane];
        float sv  = sqrtf(fmaxf(lam, 0.f));
        sR[lane] = (sv > THRESH_F) ? (1.f - THRESH_F / sv) : 0.f;
    }
    __syncwarp();

    // ---- W = V diag(r) V^T, written in place over sG (G is dead now)
    #pragma unroll
    for (int i = 0; i < 8; i++) {
        int e = lane + i * 32;
        int j = e >> 4, kk = e & 15;
        float acc = 0.f;
        #pragma unroll
        for (int i2 = 0; i2 < 16; i2++)
            acc += sV[j * 17 + i2] * (sR[i2] * sV[kk * 17 + i2]);
        sG[j * 17 + kk] = acc;
    }
    __syncwarp();

    // ---- out = m @ W -> scratch [n][a][bi][li][bj][lj] (32B-contiguous lj)
    #pragma unroll
    for (int i = 0; i < 32; i++) {
        int e = lane + i * 32;
        int a = e >> 6;
        int p = e & 63;
        int li = p >> 3, lj = p & 7;
        float acc = 0.f;
        #pragma unroll
        for (int j = 0; j < 16; j++)
            acc += sm[p * 17 + j] * sG[j * 17 + a];
        g_scratch[(((size_t)(n * AA + a) * NB + bi) * 8 + li) * SEG + bj * 8 + lj] = acc;
    }
}

// ---------------------------------------------------------------------------
// Pass 2: one CTA per output row (n,a,h). Each scratch element feeds exactly
// one pixel, so this is a pure gather-sum: stage the <=2 contributing
// 760-float segments in smem, sum <=4 contributions per pixel, normalize.
// Deterministic (fixed summation order), atomic-free, fully coalesced.
// ---------------------------------------------------------------------------
__global__ __launch_bounds__(128) void llr_pass2(const float* __restrict__ bw,
                                                 float* __restrict__ out) {
    __shared__ float seg[2][SEG];

    const int cta = blockIdx.x;
    const int h   = cta % HH;
    const int na  = cta / HH;          // n*AA + a
    const int t   = threadIdx.x;

    const int bi_lo = max(0, (h - 4) >> 2);        // == ceil((h-7)/4)
    const int bi_hi = min(NB - 1, h >> 2);
    const int nbi   = bi_hi - bi_lo + 1;           // 1 or 2

    for (int b = 0; b < nbi; b++) {
        int bi = bi_lo + b;
        int li = h - bi * STR;
        const float* src = g_scratch + (((size_t)na * NB + bi) * 8 + li) * SEG;
        for (int i = t; i < SEG; i += 128) seg[b][i] = src[i];
    }
    __syncthreads();

    #pragma unroll
    for (int i = 0; i < 3; i++) {
        int w = t + i * 128;
        int bj_lo = max(0, (w - 4) >> 2);
        int bj_hi = min(NB - 1, w >> 2);
        float acc = 0.f;
        for (int b = 0; b < nbi; b++)
            for (int bj = bj_lo; bj <= bj_hi; bj++)
                acc += seg[b][bj * 8 + (w - bj * STR)];
        out[((size_t)na * HH + h) * WW + w] = acc / bw[h * WW + w];
    }
}

// ---------------------------------------------------------------------------
extern "C" void kernel_launch(void* const* d_in, const int* in_sizes, int n_in,
                              void* d_out, int out_size) {
    (void)n_in; (void)out_size;
    const float* x;
    const float* bw;
    if (in_sizes[0] == NN * AA * HH * WW) { x = (const float*)d_in[0]; bw = (const float*)d_in[1]; }
    else                                  { x = (const float*)d_in[1]; bw = (const float*)d_in[0]; }
    float* out = (float*)d_out;

    llr_pass1<<<(NN * NBLK) / 4, 128>>>(x);
    llr_pass2<<<NN * AA * HH, 128>>>(bw, out);
}

// round 10
// speedup vs baseline: 1.6274x; 1.0796x over previous
#include <cuda_runtime.h>
#include <cuda_bf16.h>

#define NN   4
#define AA   16
#define HH   384
#define WW   384
#define BSZ  8
#define STR  4
#define NB   95
#define NBLK (NB*NB)
#define SEG  (NB*8)          // 760 floats: one (n,a,bi,li) row of block outputs
#define NSWEEP 5
#define THRESH_F 2.0f
#define ASTRIDE (NB*8*SEG)   // 577600: scratch stride per (n*AA+a)

// Block outputs staged here: layout [n][a][bi][li][bj][lj]
// size = 4*16*95*8*95*8 = 36,966,400 floats = ~148 MB (static device array: allowed)
__device__ float g_scratch[(size_t)NN * AA * NB * 8 * NB * 8];

// Per-warp smem slice layout (floats):
//   [0,1088)    m[64][17]   (pad 17 -> conflict-free column reads)
//   [1088,1360) G[16][17]   (reused for W after eigensolve)
//   [1360,1632) V[16][17]
//   [1632,1648) r[16]       spectral ratios
#define WSM 1648

// ---------------------------------------------------------------------------
// Pass 1: one WARP per (n, block). 4 matrices per CTA, fully independent
// warps. __launch_bounds__(128, 8) caps regs at 64 so all 8 CTAs (32 warps)
// fit per SM alongside the 26.4KB smem — occupancy was the R8 limiter.
// ---------------------------------------------------------------------------
__global__ __launch_bounds__(128, 8) void llr_pass1(const float* __restrict__ x) {
    __shared__ float sh[4 * WSM];

    const int wid  = threadIdx.x >> 5;
    const int lane = threadIdx.x & 31;
    float* sm = sh + wid * WSM;
    float* sG = sm + 1088;        // becomes W later
    float* sV = sm + 1360;
    float* sR = sm + 1632;

    const int id  = blockIdx.x * 4 + wid;        // matrix id 0..36099
    const int n   = id / NBLK;
    const int blk = id - n * NBLK;
    const int bi  = blk / NB;
    const int bj  = blk - bi * NB;

    // ---- gather m: 1024 elements, 32 per lane; lj runs are 32B-contiguous.
    // All-int32 addressing (x has 9.4M elements).
    {
        const int xbase = (n * AA * HH + bi * STR) * WW + bj * STR;
        #pragma unroll 4
        for (int i = 0; i < 32; i++) {
            int e = lane + i * 32;
            int a = e >> 6;           // 0..15
            int p = e & 63;           // 0..63
            int li = p >> 3, lj = p & 7;
            sm[p * 17 + a] = x[xbase + a * (HH * WW) + li * WW + lj];
        }
    }
    __syncwarp();

    // ---- G = m^T m (256 entries, 8 per lane), init V = I
    #pragma unroll 2
    for (int i = 0; i < 8; i++) {
        int e = lane + i * 32;
        int j = e >> 4, kk = e & 15;
        float acc = 0.f;
        #pragma unroll 16
        for (int p = 0; p < 64; p++) acc += sm[p * 17 + j] * sm[p * 17 + kk];
        sG[j * 17 + kk] = acc;
        sV[j * 17 + kk] = (j == kk) ? 1.f : 0.f;
    }
    __syncwarp();

    // ---- parallel cyclic Jacobi: 8 disjoint rotations per round (tournament
    //      pairing), 15 rounds/sweep. All 4 lanes of a pair compute (c,s)
    //      redundantly (branchless) from identical smem reads.
    {
        const int k   = lane >> 2;      // pair id 0..7
        const int sub = lane & 3;       // row/col segment 0..3
        const int r0  = sub * 4;

        for (int it = 0; it < NSWEEP * 15; it++) {
            int r = it % 15;
            int p, q;
            if (k == 0) { p = 15; q = r; }
            else        { p = (r + k) % 15; q = (r + 15 - k) % 15; }

            // branchless rotation params (apq==0 -> tau=+-inf -> tt=0 -> c=1,s=0)
            float apq = sG[p * 17 + q];
            float app = sG[p * 17 + p], aqq = sG[q * 17 + q];
            float d2  = 2.f * apq;
            d2 = (fabsf(d2) > 1e-30f) ? d2 : 1e-30f;
            float tau = __fdividef(aqq - app, d2);
            float tt  = __fdividef(1.f, fabsf(tau) + sqrtf(1.f + tau * tau));
            tt = (tau < 0.f) ? -tt : tt;
            float c = rsqrtf(1.f + tt * tt);
            float s = tt * c;
            __syncwarp();   // params fully read before any G write

            float np[4], nq[4];

            // Phase A: G <- G*J (columns p,q; this lane's 4 rows)
            #pragma unroll
            for (int i2 = 0; i2 < 4; i2++) {
                float a1 = sG[(r0 + i2) * 17 + p], a2 = sG[(r0 + i2) * 17 + q];
                np[i2] = c * a1 - s * a2;
                nq[i2] = s * a1 + c * a2;
            }
            #pragma unroll
            for (int i2 = 0; i2 < 4; i2++) {
                sG[(r0 + i2) * 17 + p] = np[i2];
                sG[(r0 + i2) * 17 + q] = nq[i2];
            }
            __syncwarp();

            // Phase B: G <- J^T*G (rows p,q; this lane's 4 columns)
            #pragma unroll
            for (int i2 = 0; i2 < 4; i2++) {
                float a1 = sG[p * 17 + r0 + i2], a2 = sG[q * 17 + r0 + i2];
                np[i2] = c * a1 - s * a2;
                nq[i2] = s * a1 + c * a2;
            }
            #pragma unroll
            for (int i2 = 0; i2 < 4; i2++) {
                sG[p * 17 + r0 + i2] = np[i2];
                sG[q * 17 + r0 + i2] = nq[i2];
            }

            // Phase C: V <- V*J. Independent of G; ordering vs next iter's
            // V access is covered by the two syncs inside the next iteration,
            // so no extra __syncwarp needed here for V. The final sync below
            // orders B's G writes before next param read.
            #pragma unroll
            for (int i2 = 0; i2 < 4; i2++) {
                float a1 = sV[(r0 + i2) * 17 + p], a2 = sV[(r0 + i2) * 17 + q];
                np[i2] = c * a1 - s * a2;
                nq[i2] = s * a1 + c * a2;
            }
            #pragma unroll
            for (int i2 = 0; i2 < 4; i2++) {
                sV[(r0 + i2) * 17 + p] = np[i2];
                sV[(r0 + i2) * 17 + q] = nq[i2];
            }
            __syncwarp();
        }
    }

    // ---- spectral soft-threshold ratios: r_i = max(sqrt(l)-T, 0)/sqrt(l)
    if (lane < 16) {
        float lam = sG[lane * 17 + lane];
        float sv  = sqrtf(fmaxf(lam, 0.f));
        sR[lane] = (sv > THRESH_F) ? (1.f - __fdividef(THRESH_F, sv)) : 0.f;
    }
    __syncwarp();

    // ---- W = V diag(r) V^T, written in place over sG (G is dead now)
    #pragma unroll 2
    for (int i = 0; i < 8; i++) {
        int e = lane + i * 32;
        int j = e >> 4, kk = e & 15;
        float acc = 0.f;
        #pragma unroll
        for (int i2 = 0; i2 < 16; i2++)
            acc += sV[j * 17 + i2] * (sR[i2] * sV[kk * 17 + i2]);
        sG[j * 17 + kk] = acc;
    }
    __syncwarp();

    // ---- out = m @ W -> scratch [n][a][bi][li][bj][lj] (32B-contiguous lj).
    // Scratch has 36.9M elements: int32 indexing throughout.
    {
        const int sbase = n * (AA * ASTRIDE) + bi * (8 * SEG) + bj * 8;
        #pragma unroll 2
        for (int i = 0; i < 32; i++) {
            int e = lane + i * 32;
            int a = e >> 6;
            int p = e & 63;
            int li = p >> 3, lj = p & 7;
            float acc = 0.f;
            #pragma unroll
            for (int j = 0; j < 16; j++)
                acc += sm[p * 17 + j] * sG[j * 17 + a];
            g_scratch[sbase + a * ASTRIDE + li * SEG + lj] = acc;
        }
    }
}

// ---------------------------------------------------------------------------
// Pass 2: one CTA per output row (n,a,h). Each scratch element feeds exactly
// one pixel, so this is a pure gather-sum: stage the <=2 contributing
// 760-float segments in smem, sum <=4 contributions per pixel, normalize.
// Deterministic (fixed summation order), atomic-free, fully coalesced.
// ---------------------------------------------------------------------------
__global__ __launch_bounds__(128) void llr_pass2(const float* __restrict__ bw,
                                                 float* __restrict__ out) {
    __shared__ float seg[2][SEG];

    const int cta = blockIdx.x;
    const int h   = cta % HH;
    const int na  = cta / HH;          // n*AA + a
    const int t   = threadIdx.x;

    const int bi_lo = max(0, (h - 4) >> 2);        // == ceil((h-7)/4)
    const int bi_hi = min(NB - 1, h >> 2);
    const int nbi   = bi_hi - bi_lo + 1;           // 1 or 2

    for (int b = 0; b < nbi; b++) {
        int bi = bi_lo + b;
        int li = h - bi * STR;
        const float* src = g_scratch + na * ASTRIDE + (bi * 8 + li) * SEG;
        for (int i = t; i < SEG; i += 128) seg[b][i] = src[i];
    }
    __syncthreads();

    #pragma unroll
    for (int i = 0; i < 3; i++) {
        int w = t + i * 128;
        int bj_lo = max(0, (w - 4) >> 2);
        int bj_hi = min(NB - 1, w >> 2);
        float acc = 0.f;
        for (int b = 0; b < nbi; b++)
            for (int bj = bj_lo; bj <= bj_hi; bj++)
                acc += seg[b][bj * 8 + (w - bj * STR)];
        out[(na * HH + h) * WW + w] = acc / bw[h * WW + w];
    }
}

// ---------------------------------------------------------------------------
extern "C" void kernel_launch(void* const* d_in, const int* in_sizes, int n_in,
                              void* d_out, int out_size) {
    (void)n_in; (void)out_size;
    const float* x;
    const float* bw;
    if (in_sizes[0] == NN * AA * HH * WW) { x = (const float*)d_in[0]; bw = (const float*)d_in[1]; }
    else                                  { x = (const float*)d_in[1]; bw = (const float*)d_in[0]; }
    float* out = (float*)d_out;

    llr_pass1<<<(NN * NBLK) / 4, 128>>>(x);
    llr_pass2<<<NN * AA * HH, 128>>>(bw, out);
}

// round 11
// speedup vs baseline: 2.1501x; 1.3212x over previous
#include <cuda_runtime.h>
#include <cuda_bf16.h>

#define NN   4
#define AA   16
#define HH   384
#define WW   384
#define BSZ  8
#define STR  4
#define NB   95
#define NBLK (NB*NB)
#define SEG  (NB*8)          // 760 floats: one (n,a,bi,li) row of block outputs
#define NSWEEP 4
#define THRESH_F 2.0f
#define ASTRIDE (NB*8*SEG)   // 577600: scratch stride per (n*AA+a)

// Block outputs staged here: layout [n][a][bi][li][bj][lj]
// size = 4*16*95*8*95*8 = 36,966,400 floats = ~148 MB (static device array: allowed)
__device__ float g_scratch[(size_t)NN * AA * NB * 8 * NB * 8];

// Per-warp smem slice layout (floats):
//   [0,1088)    m[64][17]   (pad 17 -> conflict-free column reads)
//   [1088,1360) G[16][17]   (reused for W after eigensolve)
//   [1360,1632) V[16][17]
//   [1632,1648) r[16]       spectral ratios
#define WSM 1648

// ---------------------------------------------------------------------------
// Pass 1: one WARP per (n, block). 4 matrices per CTA, independent warps.
// Crossbar (128B/cyc/SM) is the binding pipe -> all dense stages are
// register-tiled to minimize warp-level LDS count.
// ---------------------------------------------------------------------------
__global__ __launch_bounds__(128, 6) void llr_pass1(const float* __restrict__ x) {
    __shared__ float sh[4 * WSM];

    const int wid  = threadIdx.x >> 5;
    const int lane = threadIdx.x & 31;
    float* sm = sh + wid * WSM;
    float* sG = sm + 1088;        // becomes W later
    float* sV = sm + 1360;
    float* sR = sm + 1632;

    const int id  = blockIdx.x * 4 + wid;        // matrix id 0..36099
    const int n   = id / NBLK;
    const int blk = id - n * NBLK;
    const int bi  = blk / NB;
    const int bj  = blk - bi * NB;

    // lane tiling helpers
    const int jg = lane >> 2;        // 0..7
    const int kg = lane & 3;         // 0..3
    const int j0 = jg * 2;           // 2-row tile base (Gram / Wvr)
    const int k0 = kg * 4;           // 4-col tile base

    // ---- gather m: 1024 elements, 32 per lane; lj runs are 32B-contiguous
    {
        const int xbase = (n * AA * HH + bi * STR) * WW + bj * STR;
        #pragma unroll 4
        for (int i = 0; i < 32; i++) {
            int e = lane + i * 32;
            int a = e >> 6;           // 0..15
            int p = e & 63;           // 0..63
            int li = p >> 3, lj = p & 7;
            sm[p * 17 + a] = x[xbase + a * (HH * WW) + li * WW + lj];
        }
    }
    __syncwarp();

    // ---- G = m^T m, register-tiled 2x4 per lane: 6 LDS/p instead of 16.
    {
        float gacc[2][4] = {{0.f,0.f,0.f,0.f},{0.f,0.f,0.f,0.f}};
        #pragma unroll 8
        for (int p = 0; p < 64; p++) {
            const float* row = sm + p * 17;
            float a0 = row[j0], a1 = row[j0 + 1];
            #pragma unroll
            for (int c = 0; c < 4; c++) {
                float b = row[k0 + c];
                gacc[0][c] += a0 * b;
                gacc[1][c] += a1 * b;
            }
        }
        #pragma unroll
        for (int r = 0; r < 2; r++)
            #pragma unroll
            for (int c = 0; c < 4; c++)
                sG[(j0 + r) * 17 + k0 + c] = gacc[r][c];
        // V = I (8 entries per lane)
        #pragma unroll
        for (int i = 0; i < 8; i++) {
            int e = lane + i * 32;
            int j = e >> 4, kk = e & 15;
            sV[j * 17 + kk] = (j == kk) ? 1.f : 0.f;
        }
    }
    __syncwarp();

    // ---- parallel cyclic Jacobi: 8 disjoint rotations per round (tournament
    //      pairing), 15 rounds/sweep. All 4 lanes of a pair compute (c,s)
    //      redundantly (branchless) from identical smem reads.
    {
        const int k   = lane >> 2;      // pair id 0..7
        const int sub = lane & 3;       // row/col segment 0..3
        const int r0  = sub * 4;

        for (int it = 0; it < NSWEEP * 15; it++) {
            int r = it % 15;
            int p, q;
            if (k == 0) { p = 15; q = r; }
            else        { p = (r + k) % 15; q = (r + 15 - k) % 15; }

            // branchless rotation params
            float apq = sG[p * 17 + q];
            float app = sG[p * 17 + p], aqq = sG[q * 17 + q];
            float d2  = 2.f * apq;
            d2 = (fabsf(d2) > 1e-30f) ? d2 : 1e-30f;
            float tau = __fdividef(aqq - app, d2);
            float tt  = __fdividef(1.f, fabsf(tau) + sqrtf(1.f + tau * tau));
            tt = (tau < 0.f) ? -tt : tt;
            float c = rsqrtf(1.f + tt * tt);
            float s = tt * c;
            __syncwarp();   // params fully read before any G write

            float np[4], nq[4];

            // Phase A: G <- G*J (columns p,q; this lane's 4 rows)
            #pragma unroll
            for (int i2 = 0; i2 < 4; i2++) {
                float a1 = sG[(r0 + i2) * 17 + p], a2 = sG[(r0 + i2) * 17 + q];
                np[i2] = c * a1 - s * a2;
                nq[i2] = s * a1 + c * a2;
            }
            #pragma unroll
            for (int i2 = 0; i2 < 4; i2++) {
                sG[(r0 + i2) * 17 + p] = np[i2];
                sG[(r0 + i2) * 17 + q] = nq[i2];
            }
            __syncwarp();

            // Phase B: G <- J^T*G (rows p,q; this lane's 4 columns)
            #pragma unroll
            for (int i2 = 0; i2 < 4; i2++) {
                float a1 = sG[p * 17 + r0 + i2], a2 = sG[q * 17 + r0 + i2];
                np[i2] = c * a1 - s * a2;
                nq[i2] = s * a1 + c * a2;
            }
            #pragma unroll
            for (int i2 = 0; i2 < 4; i2++) {
                sG[p * 17 + r0 + i2] = np[i2];
                sG[q * 17 + r0 + i2] = nq[i2];
            }

            // Phase C: V <- V*J (independent of G; ordering vs next iter's
            // param read is fenced by the final syncwarp below)
            #pragma unroll
            for (int i2 = 0; i2 < 4; i2++) {
                float a1 = sV[(r0 + i2) * 17 + p], a2 = sV[(r0 + i2) * 17 + q];
                np[i2] = c * a1 - s * a2;
                nq[i2] = s * a1 + c * a2;
            }
            #pragma unroll
            for (int i2 = 0; i2 < 4; i2++) {
                sV[(r0 + i2) * 17 + p] = np[i2];
                sV[(r0 + i2) * 17 + q] = nq[i2];
            }
            __syncwarp();
        }
    }

    // ---- spectral soft-threshold ratios: r_i = max(sqrt(l)-T, 0)/sqrt(l)
    if (lane < 16) {
        float lam = sG[lane * 17 + lane];
        float sv  = sqrtf(fmaxf(lam, 0.f));
        sR[lane] = (sv > THRESH_F) ? (1.f - __fdividef(THRESH_F, sv)) : 0.f;
    }
    __syncwarp();

    // ---- W = V diag(r) V^T, register-tiled 2x4 per lane, in place over sG
    {
        float wacc[2][4] = {{0.f,0.f,0.f,0.f},{0.f,0.f,0.f,0.f}};
        #pragma unroll
        for (int i2 = 0; i2 < 16; i2++) {
            float rr = sR[i2];
            float a0 = sV[j0 * 17 + i2], a1 = sV[(j0 + 1) * 17 + i2];
            #pragma unroll
            for (int c = 0; c < 4; c++) {
                float b = rr * sV[(k0 + c) * 17 + i2];
                wacc[0][c] += a0 * b;
                wacc[1][c] += a1 * b;
            }
        }
        __syncwarp();   // all sG (old G) reads done before overwrite with W
        #pragma unroll
        for (int r = 0; r < 2; r++)
            #pragma unroll
            for (int c = 0; c < 4; c++)
                sG[(j0 + r) * 17 + k0 + c] = wacc[r][c];
    }
    __syncwarp();

    // ---- out = m @ W, register-tiled 8p(stride 8)x4a per lane:
    //      12 LDS per j-step instead of 64. p = pg + 8r -> li = r, lj = pg.
    {
        const int pg  = jg;            // 0..7, bank-conflict-free (stride-1)
        const int a0c = kg * 4;        // a-tile base
        const int sbase = n * (AA * ASTRIDE) + bi * (8 * SEG) + bj * 8;

        float acc[4][8];
        #pragma unroll
        for (int c = 0; c < 4; c++)
            #pragma unroll
            for (int r = 0; r < 8; r++) acc[c][r] = 0.f;

        #pragma unroll 4
        for (int j = 0; j < 16; j++) {
            float wv[4];
            #pragma unroll
            for (int c = 0; c < 4; c++) wv[c] = sG[j * 17 + a0c + c];
            #pragma unroll
            for (int r = 0; r < 8; r++) {
                float mv = sm[(pg + 8 * r) * 17 + j];
                #pragma unroll
                for (int c = 0; c < 4; c++) acc[c][r] += mv * wv[c];
            }
        }
        #pragma unroll
        for (int c = 0; c < 4; c++) {
            int abase = sbase + (a0c + c) * ASTRIDE + pg;
            #pragma unroll
            for (int r = 0; r < 8; r++)
                g_scratch[abase + r * SEG] = acc[c][r];
        }
    }
}

// ---------------------------------------------------------------------------
// Pass 2: one CTA per output row (n,a,h). Pure gather-sum: stage the <=2
// contributing 760-float segments in smem, sum <=4 contributions per pixel,
// normalize. Deterministic, atomic-free, fully coalesced.
// ---------------------------------------------------------------------------
__global__ __launch_bounds__(128) void llr_pass2(const float* __restrict__ bw,
                                                 float* __restrict__ out) {
    __shared__ float seg[2][SEG];

    const int cta = blockIdx.x;
    const int h   = cta % HH;
    const int na  = cta / HH;          // n*AA + a
    const int t   = threadIdx.x;

    const int bi_lo = max(0, (h - 4) >> 2);        // == ceil((h-7)/4)
    const int bi_hi = min(NB - 1, h >> 2);
    const int nbi   = bi_hi - bi_lo + 1;           // 1 or 2

    for (int b = 0; b < nbi; b++) {
        int bi = bi_lo + b;
        int li = h - bi * STR;
        const float* src = g_scratch + na * ASTRIDE + (bi * 8 + li) * SEG;
        for (int i = t; i < SEG; i += 128) seg[b][i] = src[i];
    }
    __syncthreads();

    #pragma unroll
    for (int i = 0; i < 3; i++) {
        int w = t + i * 128;
        int bj_lo = max(0, (w - 4) >> 2);
        int bj_hi = min(NB - 1, w >> 2);
        float acc = 0.f;
        for (int b = 0; b < nbi; b++)
            for (int bj = bj_lo; bj <= bj_hi; bj++)
                acc += seg[b][bj * 8 + (w - bj * STR)];
        out[(na * HH + h) * WW + w] = acc / bw[h * WW + w];
    }
}

// ---------------------------------------------------------------------------
extern "C" void kernel_launch(void* const* d_in, const int* in_sizes, int n_in,
                              void* d_out, int out_size) {
    (void)n_in; (void)out_size;
    const float* x;
    const float* bw;
    if (in_sizes[0] == NN * AA * HH * WW) { x = (const float*)d_in[0]; bw = (const float*)d_in[1]; }
    else                                  { x = (const float*)d_in[1]; bw = (const float*)d_in[0]; }
    float* out = (float*)d_out;

    llr_pass1<<<(NN * NBLK) / 4, 128>>>(x);
    llr_pass2<<<NN * AA * HH, 128>>>(bw, out);
}